// round 3
// baseline (speedup 1.0000x reference)
#include <cuda_runtime.h>

#define NCLS 10
#define DD   128
#define WPB  4                    // warps per block
#define TPB  (WPB * 32)           // 128 threads
#define NBLK 592                  // 4 blocks/SM * 148 SMs -> one wave

// per-warp private accumulator layout (floats):
//   [0, 1280)        sums[10][128]
//   [1280, 1600)     rssq partials [10][32]  (per lane)
//   [1600, 1610)     counts[10]              (lane 0 only)
//   pad to 1616 floats
#define W_RSSQ (NCLS * DD)            // 1280
#define W_CNT  (W_RSSQ + NCLS * 32)   // 1600
#define WSTP   1616                   // floats per warp region (16B-aligned: 6464 B)

__device__ float g_sums[NCLS * DD];
__device__ float g_rssq[NCLS];
__device__ float g_cnt[NCLS];

__global__ void zero_k() {
    int i = threadIdx.x + blockIdx.x * blockDim.x;
    if (i < NCLS * DD) g_sums[i] = 0.0f;
    if (i < NCLS) { g_rssq[i] = 0.0f; g_cnt[i] = 0.0f; }
}

__global__ __launch_bounds__(TPB) void acc_k(const float4* __restrict__ x4,
                                             const int* __restrict__ t,
                                             int n) {
    __shared__ __align__(16) float sm[WPB * WSTP];
    const int lane = threadIdx.x & 31;
    const int warp = threadIdx.x >> 5;
    float* ws = sm + warp * WSTP;

    for (int i = threadIdx.x; i < WPB * WSTP; i += TPB) sm[i] = 0.0f;
    __syncthreads();

    const int gw = blockIdx.x * WPB + warp;   // global warp id
    const int W  = gridDim.x * WPB;           // total warps = 2368

#define PROC(tt, vv) do {                                                   \
        float p_ = vv.x * vv.x + vv.y * vv.y + vv.z * vv.z + vv.w * vv.w;   \
        float4* sp_ = reinterpret_cast<float4*>(ws + (tt) * DD) + lane;     \
        float4 c_ = *sp_;                                                   \
        c_.x += vv.x; c_.y += vv.y; c_.z += vv.z; c_.w += vv.w;             \
        *sp_ = c_;                                                          \
        ws[W_RSSQ + (tt) * 32 + lane] += p_;                                \
        if (lane == 0) ws[W_CNT + (tt)] += 1.0f;                            \
    } while (0)

    int i = gw;
    // 4-row unrolled grid-stride loop: batch the loads, then RMW in order
    // (in-order per-thread smem ops keep same-class batches correct).
    for (; i + 3 * W < n; i += 4 * W) {
        int    t0 = t[i],           t1 = t[i + W];
        int    t2 = t[i + 2 * W],   t3 = t[i + 3 * W];
        float4 v0 = x4[(size_t)(i)         * 32 + lane];
        float4 v1 = x4[(size_t)(i + W)     * 32 + lane];
        float4 v2 = x4[(size_t)(i + 2 * W) * 32 + lane];
        float4 v3 = x4[(size_t)(i + 3 * W) * 32 + lane];
        PROC(t0, v0); PROC(t1, v1); PROC(t2, v2); PROC(t3, v3);
    }
    for (; i < n; i += W) {
        int    tt = t[i];
        float4 vv = x4[(size_t)i * 32 + lane];
        PROC(tt, vv);
    }
#undef PROC

    __syncthreads();

    // combine the WPB warp-private copies, flush once per block
    for (int idx = threadIdx.x; idx < NCLS * DD; idx += TPB) {
        float s = 0.0f;
#pragma unroll
        for (int w = 0; w < WPB; w++) s += sm[w * WSTP + idx];
        atomicAdd(&g_sums[idx], s);
    }
    if (threadIdx.x < NCLS) {
        int c = threadIdx.x;
        float r = 0.0f, cn = 0.0f;
#pragma unroll
        for (int w = 0; w < WPB; w++) {
            for (int l = 0; l < 32; l++) r += sm[w * WSTP + W_RSSQ + c * 32 + l];
            cn += sm[w * WSTP + W_CNT + c];
        }
        atomicAdd(&g_rssq[c], r);
        atomicAdd(&g_cnt[c], cn);
    }
}

__global__ void fin_k(float* __restrict__ out) {
    __shared__ float cross[NCLS];
    int d = threadIdx.x;  // 128 threads, one per feature
    if (d < NCLS) cross[d] = 0.0f;
    __syncthreads();
#pragma unroll
    for (int c = 0; c < NCLS; c++) {
        float s = g_sums[c * DD + d];
        atomicAdd(&cross[c], s * s);
    }
    __syncthreads();
    if (d == 0) {
        double acc = 0.0;
        for (int c = 0; c < NCLS; c++) {
            double nc = (double)g_cnt[c];
            acc += ((double)g_rssq[c] - (double)cross[c] / nc) / (nc - 1.0);
        }
        out[0] = (float)(acc / NCLS);
    }
}

extern "C" void kernel_launch(void* const* d_in, const int* in_sizes, int n_in,
                              void* d_out, int out_size) {
    const float4* x4 = (const float4*)d_in[0];   // x: [N, 128] fp32
    const int*    t  = (const int*)d_in[1];      // t: [N] int32
    const int n = in_sizes[1];                   // N = row count

    zero_k<<<(NCLS * DD + 255) / 256, 256>>>();
    acc_k<<<NBLK, TPB>>>(x4, t, n);
    fin_k<<<1, DD>>>((float*)d_out);
}

// round 4
// speedup vs baseline: 1.1869x; 1.1869x over previous
#include <cuda_runtime.h>

#define NCLS 10
#define DD   128
#define WPB  4                    // warps per block
#define TPB  (WPB * 32)           // 128 threads
#define NBLK 1184                 // 8 blocks/SM * 148 SMs -> one wave, 32 warps/SM

// per-warp private accumulator layout (floats):
//   [0, 1280)        sums[10][128]
//   [1280, 1600)     rssq partials [10][32]  (per lane)
//   [1600, 1610)     counts[10]              (lane 0 only)
#define W_RSSQ (NCLS * DD)            // 1280
#define W_CNT  (W_RSSQ + NCLS * 32)   // 1600
#define WSTP   1616                   // floats per warp region (6464 B)

__device__ float g_sums[NCLS * DD];   // zero-initialized at module load;
__device__ float g_rssq[NCLS];        // fin_k re-zeros after every use.
__device__ float g_cnt[NCLS];

__global__ __launch_bounds__(TPB, 8) void acc_k(const float4* __restrict__ x4,
                                                const int* __restrict__ t,
                                                int n) {
    __shared__ __align__(16) float sm[WPB * WSTP];
    const int lane = threadIdx.x & 31;
    const int warp = threadIdx.x >> 5;
    float* ws = sm + warp * WSTP;

    for (int i = threadIdx.x; i < WPB * WSTP; i += TPB) sm[i] = 0.0f;
    __syncthreads();

    // contiguous per-warp chunk (chunk % 4 == 0 keeps int4 t-loads aligned)
    const int gw = blockIdx.x * WPB + warp;   // global warp id
    const int W  = NBLK * WPB;                // 4736 warps
    int chunk = (n + W - 1) / W;
    chunk = (chunk + 3) & ~3;
    const int start = gw * chunk;
    const int end   = (start + chunk < n) ? (start + chunk) : n;

#define PROC(tt, vv) do {                                                   \
        float p_ = vv.x * vv.x + vv.y * vv.y + vv.z * vv.z + vv.w * vv.w;   \
        float4* sp_ = reinterpret_cast<float4*>(ws + (tt) * DD) + lane;     \
        float4 c_ = *sp_;                                                   \
        c_.x += vv.x; c_.y += vv.y; c_.z += vv.z; c_.w += vv.w;             \
        *sp_ = c_;                                                          \
        ws[W_RSSQ + (tt) * 32 + lane] += p_;                                \
        if (lane == 0) ws[W_CNT + (tt)] += 1.0f;                            \
    } while (0)

    int i = start;
    if (i < end) {
        const float4* xp = x4 + (size_t)i * 32 + lane;   // one base, imm offsets
        for (; i + 8 <= end; i += 8, xp += 8 * 32) {
            int4 ta = *reinterpret_cast<const int4*>(t + i);
            int4 tb = *reinterpret_cast<const int4*>(t + i + 4);
            float4 v0 = __ldcs(xp + 0 * 32);
            float4 v1 = __ldcs(xp + 1 * 32);
            float4 v2 = __ldcs(xp + 2 * 32);
            float4 v3 = __ldcs(xp + 3 * 32);
            float4 v4 = __ldcs(xp + 4 * 32);
            float4 v5 = __ldcs(xp + 5 * 32);
            float4 v6 = __ldcs(xp + 6 * 32);
            float4 v7 = __ldcs(xp + 7 * 32);
            PROC(ta.x, v0); PROC(ta.y, v1); PROC(ta.z, v2); PROC(ta.w, v3);
            PROC(tb.x, v4); PROC(tb.y, v5); PROC(tb.z, v6); PROC(tb.w, v7);
        }
        for (; i < end; i++) {
            int    tt = t[i];
            float4 vv = __ldcs(x4 + (size_t)i * 32 + lane);
            PROC(tt, vv);
        }
    }
#undef PROC

    __syncthreads();

    // combine the WPB warp-private copies, flush once per block
    for (int idx = threadIdx.x; idx < NCLS * DD; idx += TPB) {
        float s = 0.0f;
#pragma unroll
        for (int w = 0; w < WPB; w++) s += sm[w * WSTP + idx];
        atomicAdd(&g_sums[idx], s);
    }
    if (threadIdx.x < NCLS) {
        int c = threadIdx.x;
        float r = 0.0f, cn = 0.0f;
#pragma unroll
        for (int w = 0; w < WPB; w++) {
            for (int l = 0; l < 32; l++) r += sm[w * WSTP + W_RSSQ + c * 32 + l];
            cn += sm[w * WSTP + W_CNT + c];
        }
        atomicAdd(&g_rssq[c], r);
        atomicAdd(&g_cnt[c], cn);
    }
}

__global__ void fin_k(float* __restrict__ out) {
    __shared__ float cross[NCLS];
    int d = threadIdx.x;  // 128 threads, one per feature
    if (d < NCLS) cross[d] = 0.0f;
    __syncthreads();
#pragma unroll
    for (int c = 0; c < NCLS; c++) {
        float s = g_sums[c * DD + d];
        atomicAdd(&cross[c], s * s);
        g_sums[c * DD + d] = 0.0f;   // re-zero for the next replay
    }
    __syncthreads();
    if (d == 0) {
        double acc = 0.0;
        for (int c = 0; c < NCLS; c++) {
            double nc = (double)g_cnt[c];
            acc += ((double)g_rssq[c] - (double)cross[c] / nc) / (nc - 1.0);
            g_rssq[c] = 0.0f;
            g_cnt[c]  = 0.0f;
        }
        out[0] = (float)(acc / NCLS);
    }
}

extern "C" void kernel_launch(void* const* d_in, const int* in_sizes, int n_in,
                              void* d_out, int out_size) {
    const float4* x4 = (const float4*)d_in[0];   // x: [N, 128] fp32
    const int*    t  = (const int*)d_in[1];      // t: [N] int32
    const int n = in_sizes[1];                   // N = row count

    acc_k<<<NBLK, TPB>>>(x4, t, n);
    fin_k<<<1, DD>>>((float*)d_out);
}

// round 5
// speedup vs baseline: 1.3523x; 1.1394x over previous
#include <cuda_runtime.h>

#define NCLS 10
#define DD   128
#define WPB  4                    // warps per block
#define TPB  (WPB * 32)           // 128 threads
#define NBLK 1184                 // 8 blocks/SM * 148 SMs, 32 warps/SM

// per-warp private accumulator layout (floats):
//   [0, 1280)        sums[10][128]
//   [1280, 1600)     rssq partials [10][32]  (per lane)
//   [1600, 1610)     counts[10]              (lane 0 only)
#define W_RSSQ (NCLS * DD)            // 1280
#define W_CNT  (W_RSSQ + NCLS * 32)   // 1600
#define WSTP   1616                   // floats per warp region (6464 B)

// Zero-initialized at module load; the finalizing block re-zeros everything
// after each use, so every graph replay starts from clean state.
__device__ float g_sums[NCLS * DD];
__device__ float g_rssq[NCLS];
__device__ float g_cnt[NCLS];
__device__ unsigned int g_ticket;

__global__ __launch_bounds__(TPB, 8) void acc_k(const float4* __restrict__ x4,
                                                const int* __restrict__ t,
                                                int n,
                                                float* __restrict__ out) {
    __shared__ __align__(16) float sm[WPB * WSTP];
    __shared__ bool s_last;
    const int lane = threadIdx.x & 31;
    const int warp = threadIdx.x >> 5;
    float* ws = sm + warp * WSTP;

    for (int i = threadIdx.x; i < WPB * WSTP; i += TPB) sm[i] = 0.0f;
    __syncthreads();

    // contiguous per-warp chunk (chunk % 4 == 0 keeps int4 t-loads aligned)
    const int gw = blockIdx.x * WPB + warp;   // global warp id
    const int W  = NBLK * WPB;                // 4736 warps
    int chunk = (n + W - 1) / W;
    chunk = (chunk + 3) & ~3;
    const int start = gw * chunk;
    const int end   = (start + chunk < n) ? (start + chunk) : n;

#define PROC(tt, vv) do {                                                   \
        float p_ = vv.x * vv.x + vv.y * vv.y + vv.z * vv.z + vv.w * vv.w;   \
        float4* sp_ = reinterpret_cast<float4*>(ws + (tt) * DD) + lane;     \
        float4 c_ = *sp_;                                                   \
        c_.x += vv.x; c_.y += vv.y; c_.z += vv.z; c_.w += vv.w;             \
        *sp_ = c_;                                                          \
        ws[W_RSSQ + (tt) * 32 + lane] += p_;                                \
        if (lane == 0) ws[W_CNT + (tt)] += 1.0f;                            \
    } while (0)

    int i = start;
    if (i < end) {
        const float4* xp = x4 + (size_t)i * 32 + lane;   // one base, imm offsets
        for (; i + 8 <= end; i += 8, xp += 8 * 32) {
            int4 ta = *reinterpret_cast<const int4*>(t + i);
            int4 tb = *reinterpret_cast<const int4*>(t + i + 4);
            float4 v0 = __ldcs(xp + 0 * 32);
            float4 v1 = __ldcs(xp + 1 * 32);
            float4 v2 = __ldcs(xp + 2 * 32);
            float4 v3 = __ldcs(xp + 3 * 32);
            float4 v4 = __ldcs(xp + 4 * 32);
            float4 v5 = __ldcs(xp + 5 * 32);
            float4 v6 = __ldcs(xp + 6 * 32);
            float4 v7 = __ldcs(xp + 7 * 32);
            PROC(ta.x, v0); PROC(ta.y, v1); PROC(ta.z, v2); PROC(ta.w, v3);
            PROC(tb.x, v4); PROC(tb.y, v5); PROC(tb.z, v6); PROC(tb.w, v7);
        }
        for (; i < end; i++) {
            int    tt = t[i];
            float4 vv = __ldcs(x4 + (size_t)i * 32 + lane);
            PROC(tt, vv);
        }
    }
#undef PROC

    __syncthreads();

    // combine the WPB warp-private copies, flush once per block
    for (int idx = threadIdx.x; idx < NCLS * DD; idx += TPB) {
        float s = 0.0f;
#pragma unroll
        for (int w = 0; w < WPB; w++) s += sm[w * WSTP + idx];
        atomicAdd(&g_sums[idx], s);
    }
    if (threadIdx.x < NCLS) {
        int c = threadIdx.x;
        float r = 0.0f, cn = 0.0f;
#pragma unroll
        for (int w = 0; w < WPB; w++) {
            for (int l = 0; l < 32; l++) r += sm[w * WSTP + W_RSSQ + c * 32 + l];
            cn += sm[w * WSTP + W_CNT + c];
        }
        atomicAdd(&g_rssq[c], r);
        atomicAdd(&g_cnt[c], cn);
    }

    // ── last-block finalization (replaces the separate fin_k launch) ──
    __threadfence();
    if (threadIdx.x == 0)
        s_last = (atomicAdd(&g_ticket, 1u) == (unsigned)(gridDim.x - 1));
    __syncthreads();
    if (!s_last) return;

    // reuse the first NCLS floats of sm as cross[c] = ||sums[c]||^2
    float* cross = sm;
    if (threadIdx.x < NCLS) cross[threadIdx.x] = 0.0f;
    __syncthreads();
    {
        const int d = threadIdx.x;   // 128 threads, one per feature
#pragma unroll
        for (int c = 0; c < NCLS; c++) {
            float s = g_sums[c * DD + d];
            atomicAdd(&cross[c], s * s);
            g_sums[c * DD + d] = 0.0f;   // re-zero for next replay
        }
    }
    __syncthreads();
    if (threadIdx.x == 0) {
        float acc = 0.0f;
#pragma unroll
        for (int c = 0; c < NCLS; c++) {
            float nc = g_cnt[c];
            acc += (g_rssq[c] - cross[c] / nc) / (nc - 1.0f);
            g_rssq[c] = 0.0f;
            g_cnt[c]  = 0.0f;
        }
        out[0] = acc / (float)NCLS;
        g_ticket = 0u;
    }
}

extern "C" void kernel_launch(void* const* d_in, const int* in_sizes, int n_in,
                              void* d_out, int out_size) {
    const float4* x4 = (const float4*)d_in[0];   // x: [N, 128] fp32
    const int*    t  = (const int*)d_in[1];      // t: [N] int32
    const int n = in_sizes[1];                   // N = row count

    acc_k<<<NBLK, TPB>>>(x4, t, n, (float*)d_out);
}